// round 5
// baseline (speedup 1.0000x reference)
#include <cuda_runtime.h>
#include <cuda_bf16.h>

constexpr int B     = 8;
constexpr int HQ    = 32;
constexpr int HKV   = 8;
constexpr int G     = 4;
constexpr int D     = 128;
constexpr int BS    = 128;
constexpr int NCMPB = 16;
constexpr int NORIB = 64;
constexpr int NSPLIT = 16;
constexpr int PAGE_ELEMS = 2 * BS * HKV * D;
constexpr float SCALE  = 0.08838834764831845f;
constexpr float NEGINF = -1e30f;

// Allocation-free scratch
__device__ float  g_pacc[B * HKV * NSPLIT * G * D];  // 2 MB unnormalized partials
__device__ float  g_pm  [B * HKV * NSPLIT * G];
__device__ float  g_ps  [B * HKV * NSPLIT * G];
__device__ float  g_tl  [B * HKV * 3 * G];           // tail logits
__device__ float4 g_tv  [B * HKV * 3 * (D / 4)];     // tail V rows
__device__ int    g_cnt [B * HKV];                   // arrival counters (zero-init)

__device__ __forceinline__ float warp_sum(float v) {
    v += __shfl_xor_sync(0xffffffffu, v, 16);
    v += __shfl_xor_sync(0xffffffffu, v, 8);
    v += __shfl_xor_sync(0xffffffffu, v, 4);
    v += __shfl_xor_sync(0xffffffffu, v, 2);
    v += __shfl_xor_sync(0xffffffffu, v, 1);
    return v;
}
__device__ __forceinline__ float warp_max(float v) {
    v = fmaxf(v, __shfl_xor_sync(0xffffffffu, v, 16));
    v = fmaxf(v, __shfl_xor_sync(0xffffffffu, v, 8));
    v = fmaxf(v, __shfl_xor_sync(0xffffffffu, v, 4));
    v = fmaxf(v, __shfl_xor_sync(0xffffffffu, v, 2));
    v = fmaxf(v, __shfl_xor_sync(0xffffffffu, v, 1));
    return v;
}

// Merge: run by the last-arriving split CTA of (b, hkv). All inputs L2-hot.
__device__ __forceinline__ void merge_bh(int bh, int hkv,
    const float* __restrict__ sinks, float* __restrict__ out)
{
    const int tid  = threadIdx.x;
    const int base = bh * NSPLIT * G;
    const int b    = bh / HKV;

#pragma unroll
    for (int rep = 0; rep < 2; ++rep) {
        const int idx = rep * 256 + tid;          // 0..511
        const int g = idx >> 7, d = idx & 127;

        float pm[NSPLIT];
#pragma unroll
        for (int sp = 0; sp < NSPLIT; ++sp)
            pm[sp] = __ldcg(&g_pm[base + sp * G + g]);

        float tl[3];
#pragma unroll
        for (int t = 0; t < 3; ++t)
            tl[t] = __ldcg(&g_tl[(bh * 3 + t) * G + g]);

        const float sink = sinks[hkv * G + g];
        float M = sink;
#pragma unroll
        for (int sp = 0; sp < NSPLIT; ++sp) M = fmaxf(M, pm[sp]);
#pragma unroll
        for (int t = 0; t < 3; ++t) M = fmaxf(M, tl[t]);

        float S = __expf(sink - M);
        float num = 0.f;
#pragma unroll
        for (int sp = 0; sp < NSPLIT; ++sp) {
            const float w = __expf(pm[sp] - M);
            S += w * __ldcg(&g_ps[base + sp * G + g]);
            if (w > 0.f)
                num += w * __ldcg(&g_pacc[(size_t)(base + sp * G + g) * D + d]);
        }
        const float* tvf = (const float*)&g_tv[bh * 3 * (D / 4)];
#pragma unroll
        for (int t = 0; t < 3; ++t) {
            const float p = __expf(tl[t] - M);   // exactly 0 for invalid tail
            S   += p;
            num += p * tvf[t * D + d];
        }
        out[((size_t)b * HQ + hkv * G + g) * D + d] = num / S;
    }
}

// ---------------------------------------------------------------------------
// One CTA per (b, hkv, page).
//   pass 1: thread-per-token K dot (no shuffles; q broadcast from smem)
//   block softmax (warp g owns head g)
//   pass 2: warp-per-token V FMA (p broadcast from smem)
//   fused last-CTA merge
// ---------------------------------------------------------------------------
__global__ __launch_bounds__(256) void attn_kernel(
    const float* __restrict__ q,
    const float* __restrict__ cmp_kv,
    const int*   __restrict__ cmp_bt,
    const int*   __restrict__ seqused,
    const float* __restrict__ ori_kv,
    const int*   __restrict__ ori_bt,
    const float* __restrict__ sinks,
    float*       __restrict__ out)
{
    const int split = blockIdx.x % NSPLIT;
    const int bh    = blockIdx.x / NSPLIT;
    const int hkv   = bh % HKV;
    const int b     = bh / HKV;
    const int tid   = threadIdx.x;
    const int w     = tid >> 5;
    const int l     = tid & 31;

    const int seq     = seqused[b];
    const int cmp_len = seq >> 2;
    int cnt = cmp_len - split * BS;
    if (cnt > BS) cnt = BS;

    const int pmbase = (bh * NSPLIT + split) * G;

    if (cnt <= 0) {
        if (tid < G) { g_pm[pmbase + tid] = NEGINF; g_ps[pmbase + tid] = 0.f; }
    } else {
        const int page = cmp_bt[b * NCMPB + split];
        const float4* kbase = (const float4*)(cmp_kv + (size_t)page * PAGE_ELEMS + hkv * D);
        const float4* vbase = kbase + (BS * HKV * D) / 4;
        constexpr int TOKSTRIDE = HKV * D / 4;

        __shared__ __align__(16) float sm_q[G * D];          // 2 KB
        __shared__ __align__(16) float sm_p[G][BS + 4];
        __shared__ __align__(16) float sm_acc[8][G][D];      // 16 KB

        // ---- preload q (512 contiguous floats) ----
        const float4* qb4 = (const float4*)(q + ((size_t)b * HQ + hkv * G) * D);
        if (tid < G * D / 4)
            ((float4*)sm_q)[tid] = qb4[tid];
        __syncthreads();

        // ---- pass 1: thread-per-token K dot, 2 heads per thread ----
        {
            const int tok = tid & 127;
            const int hp  = tid >> 7;            // head pair: 0 -> g{0,1}, 1 -> g{2,3}
            if (tok < cnt) {
                const float4* krow = kbase + (size_t)tok * TOKSTRIDE;
                const float4* q0 = (const float4*)(sm_q + (2 * hp)     * D);
                const float4* q1 = (const float4*)(sm_q + (2 * hp + 1) * D);
                float a0 = 0.f, a1 = 0.f, b0 = 0.f, b1 = 0.f;
#pragma unroll 8
                for (int c = 0; c < D / 4; c += 2) {
                    const float4 k4a = krow[c];
                    const float4 k4b = krow[c + 1];
                    const float4 qa0 = q0[c], qb0 = q0[c + 1];
                    const float4 qa1 = q1[c], qb1 = q1[c + 1];
                    a0 += k4a.x * qa0.x + k4a.y * qa0.y + k4a.z * qa0.z + k4a.w * qa0.w;
                    a1 += k4a.x * qa1.x + k4a.y * qa1.y + k4a.z * qa1.z + k4a.w * qa1.w;
                    b0 += k4b.x * qb0.x + k4b.y * qb0.y + k4b.z * qb0.z + k4b.w * qb0.w;
                    b1 += k4b.x * qb1.x + k4b.y * qb1.y + k4b.z * qb1.z + k4b.w * qb1.w;
                }
                sm_p[2 * hp][tok]     = (a0 + b0) * SCALE;
                sm_p[2 * hp + 1][tok] = (a1 + b1) * SCALE;
            }
        }
        __syncthreads();

        // ---- block softmax numerators (warp g owns head g) ----
        if (w < G) {
            float vals[4];
            float mx = NEGINF;
#pragma unroll
            for (int i = 0; i < 4; ++i) {
                const int t = l + i * 32;
                vals[i] = (t < cnt) ? sm_p[w][t] : NEGINF;
                mx = fmaxf(mx, vals[i]);
            }
            mx = warp_max(mx);
            float s = 0.f;
#pragma unroll
            for (int i = 0; i < 4; ++i) {
                const int t = l + i * 32;
                if (t < cnt) {
                    const float p = __expf(vals[i] - mx);
                    s += p;
                    sm_p[w][t] = p;
                }
            }
            s = warp_sum(s);
            if (l == 0) { g_pm[pmbase + w] = mx; g_ps[pmbase + w] = s; }
        }
        __syncthreads();

        // ---- pass 2: warp-per-token V accumulate (pure FMA) ----
        float4 acc[G];
#pragma unroll
        for (int g = 0; g < G; ++g) acc[g] = make_float4(0.f, 0.f, 0.f, 0.f);

        if (cnt == BS) {
#pragma unroll
            for (int i = 0; i < BS / 8; ++i) {
                const int t = w + i * 8;
                const float4 v4 = vbase[(size_t)t * TOKSTRIDE + l];
#pragma unroll
                for (int g = 0; g < G; ++g) {
                    const float p = sm_p[g][t];
                    acc[g].x += p * v4.x; acc[g].y += p * v4.y;
                    acc[g].z += p * v4.z; acc[g].w += p * v4.w;
                }
            }
        } else {
            for (int t = w; t < cnt; t += 8) {
                const float4 v4 = vbase[(size_t)t * TOKSTRIDE + l];
#pragma unroll
                for (int g = 0; g < G; ++g) {
                    const float p = sm_p[g][t];
                    acc[g].x += p * v4.x; acc[g].y += p * v4.y;
                    acc[g].z += p * v4.z; acc[g].w += p * v4.w;
                }
            }
        }

#pragma unroll
        for (int g = 0; g < G; ++g)
            ((float4*)sm_acc[w][g])[l] = acc[g];
        __syncthreads();

        float* outp = g_pacc + (size_t)pmbase * D;
        for (int idx = tid; idx < G * D; idx += 256) {
            const int g = idx >> 7, d = idx & 127;
            float v = 0.f;
#pragma unroll
            for (int ww = 0; ww < 8; ++ww) v += sm_acc[ww][g][d];
            outp[idx] = v;
        }

        // ---- split 0 also computes the <=3-token original-cache tail ----
        if (split == 0 && w < 3) {
            const int cmp_base = cmp_len << 2;
            const int ntail    = seq - cmp_base;     // 0..3
            float4* tvrow = &g_tv[(bh * 3 + w) * (D / 4)];
            if (w < ntail) {
                const int pos   = cmp_base + w;
                const int opage = ori_bt[b * NORIB + (pos >> 7)];
                const float* kp = ori_kv + (size_t)opage * PAGE_ELEMS
                                  + (size_t)(pos & 127) * HKV * D + hkv * D;
                const float4 k4 = ((const float4*)kp)[l];
                const float4 v4 = ((const float4*)(kp + BS * HKV * D))[l];
                tvrow[l] = v4;
#pragma unroll
                for (int g = 0; g < G; ++g) {
                    const float4 qg = ((const float4*)(sm_q + g * D))[l];
                    float x = qg.x * k4.x + qg.y * k4.y + qg.z * k4.z + qg.w * k4.w;
                    x = warp_sum(x);
                    if (l == g) g_tl[(bh * 3 + w) * G + g] = x * SCALE;
                }
            } else {
                if (l < G) g_tl[(bh * 3 + w) * G + l] = NEGINF;
                tvrow[l] = make_float4(0.f, 0.f, 0.f, 0.f);
            }
        }
    }

    // ---- last-CTA merge (threadFenceReduction pattern) ----
    __shared__ int s_last;
    __threadfence();
    if (tid == 0) {
        const int v = atomicAdd(&g_cnt[bh], 1);
        const int last = (v == NSPLIT - 1);
        if (last) g_cnt[bh] = 0;     // reset for next graph replay
        s_last = last;
    }
    __syncthreads();
    if (s_last) {
        __threadfence();
        merge_bh(bh, hkv, sinks, out);
    }
}

extern "C" void kernel_launch(void* const* d_in, const int* in_sizes, int n_in,
                              void* d_out, int out_size) {
    const float* q       = (const float*)d_in[0];
    const float* cmp_kv  = (const float*)d_in[1];
    const float* sinks   = (const float*)d_in[2];
    const int*   cmp_bt  = (const int*)d_in[3];
    const int*   seqused = (const int*)d_in[4];
    const float* ori_kv  = (const float*)d_in[5];
    const int*   ori_bt  = (const int*)d_in[6];
    float* out = (float*)d_out;

    attn_kernel<<<B * HKV * NSPLIT, 256>>>(q, cmp_kv, cmp_bt, seqused,
                                           ori_kv, ori_bt, sinks, out);
}

// round 6
// speedup vs baseline: 1.2109x; 1.2109x over previous
#include <cuda_runtime.h>
#include <cuda_bf16.h>

constexpr int B     = 8;
constexpr int HQ    = 32;
constexpr int HKV   = 8;
constexpr int G     = 4;
constexpr int D     = 128;
constexpr int BS    = 128;
constexpr int NCMPB = 16;
constexpr int NORIB = 64;
constexpr int NSPL  = 32;          // splits per (b,hkv): half a page each
constexpr int TOK   = 64;          // tokens per CTA
constexpr int NW    = 4;           // warps per CTA
constexpr int PAGE_ELEMS = 2 * BS * HKV * D;
constexpr float SCALE  = 0.08838834764831845f;
constexpr float NEGINF = -1e30f;

// Allocation-free scratch
__device__ float  g_pacc[B * HKV * NSPL * G * D];   // 4 MB unnormalized partials
__device__ float  g_pm  [B * HKV * NSPL * G];
__device__ float  g_ps  [B * HKV * NSPL * G];
__device__ float  g_tl  [B * HKV * 3 * G];          // tail logits
__device__ float4 g_tv  [B * HKV * 3 * (D / 4)];    // tail V rows
__device__ int    g_cnt [B * HKV];                  // arrival counters (zero-init)

__device__ __forceinline__ float warp_sum(float v) {
    v += __shfl_xor_sync(0xffffffffu, v, 16);
    v += __shfl_xor_sync(0xffffffffu, v, 8);
    v += __shfl_xor_sync(0xffffffffu, v, 4);
    v += __shfl_xor_sync(0xffffffffu, v, 2);
    v += __shfl_xor_sync(0xffffffffu, v, 1);
    return v;
}
__device__ __forceinline__ float warp_max(float v) {
    v = fmaxf(v, __shfl_xor_sync(0xffffffffu, v, 16));
    v = fmaxf(v, __shfl_xor_sync(0xffffffffu, v, 8));
    v = fmaxf(v, __shfl_xor_sync(0xffffffffu, v, 4));
    v = fmaxf(v, __shfl_xor_sync(0xffffffffu, v, 2));
    v = fmaxf(v, __shfl_xor_sync(0xffffffffu, v, 1));
    return v;
}

// 4-head warp reduction in 11 shuffles: after xor16+xor8 each lane holds the
// sum over lanes congruent mod 8; lane octet g then reduces head g.
__device__ __forceinline__ void reduce4(float x0, float x1, float x2, float x3,
                                        int l, float* dst0, int stride, int t)
{
    x0 += __shfl_xor_sync(0xffffffffu, x0, 16);
    x1 += __shfl_xor_sync(0xffffffffu, x1, 16);
    x2 += __shfl_xor_sync(0xffffffffu, x2, 16);
    x3 += __shfl_xor_sync(0xffffffffu, x3, 16);
    x0 += __shfl_xor_sync(0xffffffffu, x0, 8);
    x1 += __shfl_xor_sync(0xffffffffu, x1, 8);
    x2 += __shfl_xor_sync(0xffffffffu, x2, 8);
    x3 += __shfl_xor_sync(0xffffffffu, x3, 8);
    const int g = l >> 3;
    float v = (g == 0) ? x0 : (g == 1) ? x1 : (g == 2) ? x2 : x3;
    v += __shfl_xor_sync(0xffffffffu, v, 4);
    v += __shfl_xor_sync(0xffffffffu, v, 2);
    v += __shfl_xor_sync(0xffffffffu, v, 1);
    if ((l & 7) == 0) dst0[g * stride + t] = v * SCALE;
}

// Merge: run by the last-arriving split CTA of (b, hkv). All inputs L2-hot.
__device__ __forceinline__ void merge_bh(int bh, int hkv,
    const float* __restrict__ sinks, float* __restrict__ out)
{
    const int tid  = threadIdx.x;
    const int base = bh * NSPL * G;
    const int b    = bh / HKV;

#pragma unroll
    for (int rep = 0; rep < 4; ++rep) {
        const int idx = rep * 128 + tid;          // 0..511
        const int g = idx >> 7, d = idx & 127;

        float pm[NSPL];
#pragma unroll
        for (int sp = 0; sp < NSPL; ++sp)
            pm[sp] = __ldcg(&g_pm[base + sp * G + g]);

        float tl[3];
#pragma unroll
        for (int t = 0; t < 3; ++t)
            tl[t] = __ldcg(&g_tl[(bh * 3 + t) * G + g]);

        const float sink = sinks[hkv * G + g];
        float M = sink;
#pragma unroll
        for (int sp = 0; sp < NSPL; ++sp) M = fmaxf(M, pm[sp]);
#pragma unroll
        for (int t = 0; t < 3; ++t) M = fmaxf(M, tl[t]);

        float S = __expf(sink - M);
        float num = 0.f;
#pragma unroll
        for (int sp = 0; sp < NSPL; ++sp) {
            const float w = __expf(pm[sp] - M);
            S += w * __ldcg(&g_ps[base + sp * G + g]);
            if (w > 0.f)
                num += w * __ldcg(&g_pacc[(size_t)(base + sp * G + g) * D + d]);
        }
        const float* tvf = (const float*)&g_tv[bh * 3 * (D / 4)];
#pragma unroll
        for (int t = 0; t < 3; ++t) {
            const float p = __expf(tl[t] - M);   // exactly 0 for invalid tail
            S   += p;
            num += p * tvf[t * D + d];
        }
        out[((size_t)b * HQ + hkv * G + g) * D + d] = num / S;
    }
}

// ---------------------------------------------------------------------------
// One CTA per (b, hkv, half-page). 128 threads = 4 warps, 64 tokens.
// ---------------------------------------------------------------------------
__global__ __launch_bounds__(128) void attn_kernel(
    const float* __restrict__ q,
    const float* __restrict__ cmp_kv,
    const int*   __restrict__ cmp_bt,
    const int*   __restrict__ seqused,
    const float* __restrict__ ori_kv,
    const int*   __restrict__ ori_bt,
    const float* __restrict__ sinks,
    float*       __restrict__ out)
{
    const int split = blockIdx.x % NSPL;
    const int bh    = blockIdx.x / NSPL;
    const int hkv   = bh % HKV;
    const int b     = bh / HKV;
    const int tid   = threadIdx.x;
    const int w     = tid >> 5;
    const int l     = tid & 31;

    const int seq     = seqused[b];
    const int cmp_len = seq >> 2;
    int cnt = cmp_len - split * TOK;
    if (cnt > TOK) cnt = TOK;

    const int pmbase = (bh * NSPL + split) * G;

    if (cnt <= 0) {
        if (tid < G) { g_pm[pmbase + tid] = NEGINF; g_ps[pmbase + tid] = 0.f; }
    } else {
        const int page   = cmp_bt[b * NCMPB + (split >> 1)];
        const int tokoff = (split & 1) * TOK;
        const float4* kbase = (const float4*)(cmp_kv + (size_t)page * PAGE_ELEMS + hkv * D)
                              + (size_t)tokoff * (HKV * D / 4);
        const float4* vbase = kbase + (BS * HKV * D) / 4;
        constexpr int TOKSTRIDE = HKV * D / 4;

        __shared__ __align__(16) float sm_q[G * D];              // 2 KB
        __shared__ __align__(16) float sm_p[G][TOK + 4];         // ~1.1 KB
        __shared__ __align__(16) float sm_acc[NW][G][D];         // 8 KB

        // ---- preload q (512 contiguous floats over 128 threads) ----
        ((float4*)sm_q)[tid] = ((const float4*)(q + ((size_t)b * HQ + hkv * G) * D))[tid];
        __syncthreads();

        float4 qv[G];
#pragma unroll
        for (int g = 0; g < G; ++g)
            qv[g] = ((const float4*)(sm_q + g * D))[l];

        // ---- pass 1: warp-per-token K dot (coalesced), 11-shfl reduce ----
        if (cnt == TOK) {
#pragma unroll
            for (int i = 0; i < TOK / NW; ++i) {
                const int t = w + i * NW;
                const float4 k4 = kbase[(size_t)t * TOKSTRIDE + l];
                reduce4(qv[0].x*k4.x + qv[0].y*k4.y + qv[0].z*k4.z + qv[0].w*k4.w,
                        qv[1].x*k4.x + qv[1].y*k4.y + qv[1].z*k4.z + qv[1].w*k4.w,
                        qv[2].x*k4.x + qv[2].y*k4.y + qv[2].z*k4.z + qv[2].w*k4.w,
                        qv[3].x*k4.x + qv[3].y*k4.y + qv[3].z*k4.z + qv[3].w*k4.w,
                        l, &sm_p[0][0], TOK + 4, t);
            }
        } else {
            for (int t = w; t < cnt; t += NW) {
                const float4 k4 = kbase[(size_t)t * TOKSTRIDE + l];
                reduce4(qv[0].x*k4.x + qv[0].y*k4.y + qv[0].z*k4.z + qv[0].w*k4.w,
                        qv[1].x*k4.x + qv[1].y*k4.y + qv[1].z*k4.z + qv[1].w*k4.w,
                        qv[2].x*k4.x + qv[2].y*k4.y + qv[2].z*k4.z + qv[2].w*k4.w,
                        qv[3].x*k4.x + qv[3].y*k4.y + qv[3].z*k4.z + qv[3].w*k4.w,
                        l, &sm_p[0][0], TOK + 4, t);
            }
        }
        __syncthreads();

        // ---- block softmax numerators (warp g owns head g; 64 tokens) ----
        if (w < G) {
            float vals[2];
            float mx = NEGINF;
#pragma unroll
            for (int i = 0; i < 2; ++i) {
                const int t = l + i * 32;
                vals[i] = (t < cnt) ? sm_p[w][t] : NEGINF;
                mx = fmaxf(mx, vals[i]);
            }
            mx = warp_max(mx);
            float s = 0.f;
#pragma unroll
            for (int i = 0; i < 2; ++i) {
                const int t = l + i * 32;
                if (t < cnt) {
                    const float p = __expf(vals[i] - mx);
                    s += p;
                    sm_p[w][t] = p;
                }
            }
            s = warp_sum(s);
            if (l == 0) { g_pm[pmbase + w] = mx; g_ps[pmbase + w] = s; }
        }
        __syncthreads();

        // ---- pass 2: warp-per-token V accumulate (pure FMA) ----
        float4 acc[G];
#pragma unroll
        for (int g = 0; g < G; ++g) acc[g] = make_float4(0.f, 0.f, 0.f, 0.f);

        if (cnt == TOK) {
#pragma unroll
            for (int i = 0; i < TOK / NW; ++i) {
                const int t = w + i * NW;
                const float4 v4 = vbase[(size_t)t * TOKSTRIDE + l];
#pragma unroll
                for (int g = 0; g < G; ++g) {
                    const float p = sm_p[g][t];
                    acc[g].x += p * v4.x; acc[g].y += p * v4.y;
                    acc[g].z += p * v4.z; acc[g].w += p * v4.w;
                }
            }
        } else {
            for (int t = w; t < cnt; t += NW) {
                const float4 v4 = vbase[(size_t)t * TOKSTRIDE + l];
#pragma unroll
                for (int g = 0; g < G; ++g) {
                    const float p = sm_p[g][t];
                    acc[g].x += p * v4.x; acc[g].y += p * v4.y;
                    acc[g].z += p * v4.z; acc[g].w += p * v4.w;
                }
            }
        }

#pragma unroll
        for (int g = 0; g < G; ++g)
            ((float4*)sm_acc[w][g])[l] = acc[g];
        __syncthreads();

        float* outp = g_pacc + (size_t)pmbase * D;
#pragma unroll
        for (int rep = 0; rep < 4; ++rep) {
            const int idx = rep * 128 + tid;
            const int g = idx >> 7, d = idx & 127;
            float v = 0.f;
#pragma unroll
            for (int ww = 0; ww < NW; ++ww) v += sm_acc[ww][g][d];
            outp[idx] = v;
        }

        // ---- split 0 also computes the <=3-token original-cache tail ----
        if (split == 0 && w < 3) {
            const int cmp_base = cmp_len << 2;
            const int ntail    = seq - cmp_base;     // 0..3
            float4* tvrow = &g_tv[(bh * 3 + w) * (D / 4)];
            if (w < ntail) {
                const int pos   = cmp_base + w;
                const int opage = ori_bt[b * NORIB + (pos >> 7)];
                const float* kp = ori_kv + (size_t)opage * PAGE_ELEMS
                                  + (size_t)(pos & 127) * HKV * D + hkv * D;
                const float4 k4 = ((const float4*)kp)[l];
                const float4 v4 = ((const float4*)(kp + BS * HKV * D))[l];
                tvrow[l] = v4;
#pragma unroll
                for (int g = 0; g < G; ++g) {
                    float x = qv[g].x * k4.x + qv[g].y * k4.y + qv[g].z * k4.z + qv[g].w * k4.w;
                    x = warp_sum(x);
                    if (l == g) g_tl[(bh * 3 + w) * G + g] = x * SCALE;
                }
            } else {
                if (l < G) g_tl[(bh * 3 + w) * G + l] = NEGINF;
                tvrow[l] = make_float4(0.f, 0.f, 0.f, 0.f);
            }
        }
    }

    // ---- last-CTA merge (threadFenceReduction pattern) ----
    __shared__ int s_last;
    __threadfence();
    if (tid == 0) {
        const int v = atomicAdd(&g_cnt[bh], 1);
        const int last = (v == NSPL - 1);
        if (last) g_cnt[bh] = 0;     // reset for next graph replay
        s_last = last;
    }
    __syncthreads();
    if (s_last) {
        __threadfence();
        merge_bh(bh, hkv, sinks, out);
    }
}

extern "C" void kernel_launch(void* const* d_in, const int* in_sizes, int n_in,
                              void* d_out, int out_size) {
    const float* q       = (const float*)d_in[0];
    const float* cmp_kv  = (const float*)d_in[1];
    const float* sinks   = (const float*)d_in[2];
    const int*   cmp_bt  = (const int*)d_in[3];
    const int*   seqused = (const int*)d_in[4];
    const float* ori_kv  = (const float*)d_in[5];
    const int*   ori_bt  = (const int*)d_in[6];
    float* out = (float*)d_out;

    attn_kernel<<<B * HKV * NSPL, 128>>>(q, cmp_kv, cmp_bt, seqused,
                                         ori_kv, ori_bt, sinks, out);
}

// round 7
// speedup vs baseline: 1.5857x; 1.3096x over previous
#include <cuda_runtime.h>
#include <cuda_bf16.h>

constexpr int B     = 8;
constexpr int HQ    = 32;
constexpr int HKV   = 8;
constexpr int G     = 4;
constexpr int D     = 128;
constexpr int BS    = 128;
constexpr int NCMPB = 16;
constexpr int NORIB = 64;
constexpr int NSPLIT = 16;
constexpr int PAGE_ELEMS = 2 * BS * HKV * D;
constexpr float SCALE  = 0.08838834764831845f;
constexpr float NEGINF = -1e30f;

// Allocation-free scratch
__device__ float  g_pacc[B * HKV * NSPLIT * G * D];  // 2 MB unnormalized partials
__device__ float  g_pm  [B * HKV * NSPLIT * G];
__device__ float  g_ps  [B * HKV * NSPLIT * G];
__device__ float  g_tl  [B * HKV * 3 * G];           // tail logits
__device__ float4 g_tv  [B * HKV * 3 * (D / 4)];     // tail V rows
__device__ int    g_cnt [B * HKV];                   // arrival counters (zero-init)

__device__ __forceinline__ float warp_sum(float v) {
    v += __shfl_xor_sync(0xffffffffu, v, 16);
    v += __shfl_xor_sync(0xffffffffu, v, 8);
    v += __shfl_xor_sync(0xffffffffu, v, 4);
    v += __shfl_xor_sync(0xffffffffu, v, 2);
    v += __shfl_xor_sync(0xffffffffu, v, 1);
    return v;
}
__device__ __forceinline__ float warp_max(float v) {
    v = fmaxf(v, __shfl_xor_sync(0xffffffffu, v, 16));
    v = fmaxf(v, __shfl_xor_sync(0xffffffffu, v, 8));
    v = fmaxf(v, __shfl_xor_sync(0xffffffffu, v, 4));
    v = fmaxf(v, __shfl_xor_sync(0xffffffffu, v, 2));
    v = fmaxf(v, __shfl_xor_sync(0xffffffffu, v, 1));
    return v;
}

// 4-head warp reduction in 11 shuffles. After xor16+xor8 each lane holds the
// sum over lanes congruent mod 8; lane-octet g then finishes head g's sum.
// Lanes 0,8,16,24 write heads 0..3 to sm_p[t][0..3] (consecutive floats).
__device__ __forceinline__ void reduce4(float x0, float x1, float x2, float x3,
                                        int l, float* dst /* &sm_p[t][0] */)
{
    x0 += __shfl_xor_sync(0xffffffffu, x0, 16);
    x1 += __shfl_xor_sync(0xffffffffu, x1, 16);
    x2 += __shfl_xor_sync(0xffffffffu, x2, 16);
    x3 += __shfl_xor_sync(0xffffffffu, x3, 16);
    x0 += __shfl_xor_sync(0xffffffffu, x0, 8);
    x1 += __shfl_xor_sync(0xffffffffu, x1, 8);
    x2 += __shfl_xor_sync(0xffffffffu, x2, 8);
    x3 += __shfl_xor_sync(0xffffffffu, x3, 8);
    const int g = l >> 3;
    float v = (g == 0) ? x0 : (g == 1) ? x1 : (g == 2) ? x2 : x3;
    v += __shfl_xor_sync(0xffffffffu, v, 4);
    v += __shfl_xor_sync(0xffffffffu, v, 2);
    v += __shfl_xor_sync(0xffffffffu, v, 1);
    if ((l & 7) == 0) dst[g] = v * SCALE;
}

// Merge: run by the last-arriving split CTA of (b, hkv). All inputs L2-hot.
__device__ __forceinline__ void merge_bh(int bh, int hkv,
    const float* __restrict__ sinks, float* __restrict__ out)
{
    const int tid  = threadIdx.x;
    const int base = bh * NSPLIT * G;
    const int b    = bh / HKV;

#pragma unroll
    for (int rep = 0; rep < 2; ++rep) {
        const int idx = rep * 256 + tid;          // 0..511
        const int g = idx >> 7, d = idx & 127;

        float pm[NSPLIT];
#pragma unroll
        for (int sp = 0; sp < NSPLIT; ++sp)
            pm[sp] = __ldcg(&g_pm[base + sp * G + g]);

        float tl[3];
#pragma unroll
        for (int t = 0; t < 3; ++t)
            tl[t] = __ldcg(&g_tl[(bh * 3 + t) * G + g]);

        const float sink = sinks[hkv * G + g];
        float M = sink;
#pragma unroll
        for (int sp = 0; sp < NSPLIT; ++sp) M = fmaxf(M, pm[sp]);
#pragma unroll
        for (int t = 0; t < 3; ++t) M = fmaxf(M, tl[t]);

        float S = __expf(sink - M);
        float num = 0.f;
#pragma unroll
        for (int sp = 0; sp < NSPLIT; ++sp) {
            const float w = __expf(pm[sp] - M);
            S += w * __ldcg(&g_ps[base + sp * G + g]);
            if (w > 0.f)
                num += w * __ldcg(&g_pacc[(size_t)(base + sp * G + g) * D + d]);
        }
        const float* tvf = (const float*)&g_tv[bh * 3 * (D / 4)];
#pragma unroll
        for (int t = 0; t < 3; ++t) {
            const float p = __expf(tl[t] - M);   // exactly 0 for invalid tail
            S   += p;
            num += p * tvf[t * D + d];
        }
        out[((size_t)b * HQ + hkv * G + g) * D + d] = num / S;
    }
}

// ---------------------------------------------------------------------------
// One CTA per (b, hkv, page). Two-pass flash partial + fused last-CTA merge.
// ---------------------------------------------------------------------------
__global__ __launch_bounds__(256, 4) void attn_kernel(
    const float* __restrict__ q,
    const float* __restrict__ cmp_kv,
    const int*   __restrict__ cmp_bt,
    const int*   __restrict__ seqused,
    const float* __restrict__ ori_kv,
    const int*   __restrict__ ori_bt,
    const float* __restrict__ sinks,
    float*       __restrict__ out)
{
    const int split = blockIdx.x % NSPLIT;
    const int bh    = blockIdx.x / NSPLIT;
    const int hkv   = bh % HKV;
    const int b     = bh / HKV;
    const int tid   = threadIdx.x;
    const int w     = tid >> 5;
    const int l     = tid & 31;

    const int seq     = seqused[b];
    const int cmp_len = seq >> 2;
    int cnt = cmp_len - split * BS;
    if (cnt > BS) cnt = BS;

    const int pmbase = (bh * NSPLIT + split) * G;

    if (cnt <= 0) {
        if (tid < G) { g_pm[pmbase + tid] = NEGINF; g_ps[pmbase + tid] = 0.f; }
    } else {
        const int page = cmp_bt[b * NCMPB + split];
        const float4* kbase = (const float4*)(cmp_kv + (size_t)page * PAGE_ELEMS + hkv * D);
        const float4* vbase = kbase + (BS * HKV * D) / 4;
        constexpr int TOKSTRIDE = HKV * D / 4;

        float4 qv[G];
        const float* qb = q + ((size_t)b * HQ + hkv * G) * D;
#pragma unroll
        for (int g = 0; g < G; ++g)
            qv[g] = ((const float4*)(qb + g * D))[l];

        __shared__ __align__(16) float sm_p[BS][G];      // [token][head], 2 KB
        __shared__ __align__(16) float sm_acc[8][G][D];  // 16 KB

        // ---- pass 1: warp-per-token K dot (coalesced), 11-shfl reduce ----
        if (cnt == BS) {
#pragma unroll
            for (int i = 0; i < BS / 8; ++i) {
                const int t = w + i * 8;
                const float4 k4 = kbase[(size_t)t * TOKSTRIDE + l];
                reduce4(qv[0].x*k4.x + qv[0].y*k4.y + qv[0].z*k4.z + qv[0].w*k4.w,
                        qv[1].x*k4.x + qv[1].y*k4.y + qv[1].z*k4.z + qv[1].w*k4.w,
                        qv[2].x*k4.x + qv[2].y*k4.y + qv[2].z*k4.z + qv[2].w*k4.w,
                        qv[3].x*k4.x + qv[3].y*k4.y + qv[3].z*k4.z + qv[3].w*k4.w,
                        l, &sm_p[t][0]);
            }
        } else {
            for (int t = w; t < cnt; t += 8) {
                const float4 k4 = kbase[(size_t)t * TOKSTRIDE + l];
                reduce4(qv[0].x*k4.x + qv[0].y*k4.y + qv[0].z*k4.z + qv[0].w*k4.w,
                        qv[1].x*k4.x + qv[1].y*k4.y + qv[1].z*k4.z + qv[1].w*k4.w,
                        qv[2].x*k4.x + qv[2].y*k4.y + qv[2].z*k4.z + qv[2].w*k4.w,
                        qv[3].x*k4.x + qv[3].y*k4.y + qv[3].z*k4.z + qv[3].w*k4.w,
                        l, &sm_p[t][0]);
            }
        }
        __syncthreads();

        // ---- block softmax numerators (warp g owns head g) ----
        if (w < G) {
            float vals[4];
            float mx = NEGINF;
#pragma unroll
            for (int i = 0; i < 4; ++i) {
                const int t = l + i * 32;
                vals[i] = (t < cnt) ? sm_p[t][w] : NEGINF;
                mx = fmaxf(mx, vals[i]);
            }
            mx = warp_max(mx);
            float s = 0.f;
#pragma unroll
            for (int i = 0; i < 4; ++i) {
                const int t = l + i * 32;
                if (t < cnt) {
                    const float p = __expf(vals[i] - mx);
                    s += p;
                    sm_p[t][w] = p;
                }
            }
            s = warp_sum(s);
            if (l == 0) { g_pm[pmbase + w] = mx; g_ps[pmbase + w] = s; }
        }
        __syncthreads();

        // ---- pass 2: warp-per-token V accumulate, one LDS.128 for 4 heads ----
        float4 acc[G];
#pragma unroll
        for (int g = 0; g < G; ++g) acc[g] = make_float4(0.f, 0.f, 0.f, 0.f);

        if (cnt == BS) {
#pragma unroll
            for (int i = 0; i < BS / 8; ++i) {
                const int t = w + i * 8;
                const float4 v4 = vbase[(size_t)t * TOKSTRIDE + l];
                const float4 p4 = *(const float4*)&sm_p[t][0];
                acc[0].x += p4.x * v4.x; acc[0].y += p4.x * v4.y;
                acc[0].z += p4.x * v4.z; acc[0].w += p4.x * v4.w;
                acc[1].x += p4.y * v4.x; acc[1].y += p4.y * v4.y;
                acc[1].z += p4.y * v4.z; acc[1].w += p4.y * v4.w;
                acc[2].x += p4.z * v4.x; acc[2].y += p4.z * v4.y;
                acc[2].z += p4.z * v4.z; acc[2].w += p4.z * v4.w;
                acc[3].x += p4.w * v4.x; acc[3].y += p4.w * v4.y;
                acc[3].z += p4.w * v4.z; acc[3].w += p4.w * v4.w;
            }
        } else {
            for (int t = w; t < cnt; t += 8) {
                const float4 v4 = vbase[(size_t)t * TOKSTRIDE + l];
                const float4 p4 = *(const float4*)&sm_p[t][0];
                acc[0].x += p4.x * v4.x; acc[0].y += p4.x * v4.y;
                acc[0].z += p4.x * v4.z; acc[0].w += p4.x * v4.w;
                acc[1].x += p4.y * v4.x; acc[1].y += p4.y * v4.y;
                acc[1].z += p4.y * v4.z; acc[1].w += p4.y * v4.w;
                acc[2].x += p4.z * v4.x; acc[2].y += p4.z * v4.y;
                acc[2].z += p4.z * v4.z; acc[2].w += p4.z * v4.w;
                acc[3].x += p4.w * v4.x; acc[3].y += p4.w * v4.y;
                acc[3].z += p4.w * v4.z; acc[3].w += p4.w * v4.w;
            }
        }

#pragma unroll
        for (int g = 0; g < G; ++g)
            ((float4*)sm_acc[w][g])[l] = acc[g];
        __syncthreads();

        float* outp = g_pacc + (size_t)pmbase * D;
#pragma unroll
        for (int rep = 0; rep < 2; ++rep) {
            const int idx = rep * 256 + tid;
            const int g = idx >> 7, d = idx & 127;
            float v = 0.f;
#pragma unroll
            for (int ww = 0; ww < 8; ++ww) v += sm_acc[ww][g][d];
            outp[idx] = v;
        }

        // ---- split 0 also computes the <=3-token original-cache tail ----
        if (split == 0 && w < 3) {
            const int cmp_base = cmp_len << 2;
            const int ntail    = seq - cmp_base;     // 0..3
            float4* tvrow = &g_tv[(bh * 3 + w) * (D / 4)];
            if (w < ntail) {
                const int pos   = cmp_base + w;
                const int opage = ori_bt[b * NORIB + (pos >> 7)];
                const float* kp = ori_kv + (size_t)opage * PAGE_ELEMS
                                  + (size_t)(pos & 127) * HKV * D + hkv * D;
                const float4 k4 = ((const float4*)kp)[l];
                const float4 v4 = ((const float4*)(kp + BS * HKV * D))[l];
                tvrow[l] = v4;
#pragma unroll
                for (int g = 0; g < G; ++g) {
                    float x = qv[g].x * k4.x + qv[g].y * k4.y + qv[g].z * k4.z + qv[g].w * k4.w;
                    x = warp_sum(x);
                    if (l == g) g_tl[(bh * 3 + w) * G + g] = x * SCALE;
                }
            } else {
                if (l < G) g_tl[(bh * 3 + w) * G + l] = NEGINF;
                tvrow[l] = make_float4(0.f, 0.f, 0.f, 0.f);
            }
        }
    }

    // ---- last-CTA merge (threadFenceReduction pattern) ----
    __shared__ int s_last;
    __threadfence();
    if (tid == 0) {
        const int v = atomicAdd(&g_cnt[bh], 1);
        const int last = (v == NSPLIT - 1);
        if (last) g_cnt[bh] = 0;     // reset for next graph replay
        s_last = last;
    }
    __syncthreads();
    if (s_last) {
        __threadfence();
        merge_bh(bh, hkv, sinks, out);
    }
}

extern "C" void kernel_launch(void* const* d_in, const int* in_sizes, int n_in,
                              void* d_out, int out_size) {
    const float* q       = (const float*)d_in[0];
    const float* cmp_kv  = (const float*)d_in[1];
    const float* sinks   = (const float*)d_in[2];
    const int*   cmp_bt  = (const int*)d_in[3];
    const int*   seqused = (const int*)d_in[4];
    const float* ori_kv  = (const float*)d_in[5];
    const int*   ori_bt  = (const int*)d_in[6];
    float* out = (float*)d_out;

    attn_kernel<<<B * HKV * NSPLIT, 256>>>(q, cmp_kv, cmp_bt, seqused,
                                           ori_kv, ori_bt, sinks, out);
}

// round 8
// speedup vs baseline: 1.8163x; 1.1454x over previous
#include <cuda_runtime.h>
#include <cuda_bf16.h>
#include <cstdint>

constexpr int B     = 8;
constexpr int HQ    = 32;
constexpr int HKV   = 8;
constexpr int G     = 4;
constexpr int D     = 128;
constexpr int BS    = 128;
constexpr int NCMPB = 16;
constexpr int NORIB = 64;
constexpr int NSPLIT = 16;
constexpr int PAGE_ELEMS = 2 * BS * HKV * D;
constexpr float SCALE  = 0.08838834764831845f;
constexpr float NEGINF = -1e30f;

// Allocation-free scratch
__device__ float  g_pacc[B * HKV * NSPLIT * G * D];  // 2 MB unnormalized partials
__device__ float  g_pm  [B * HKV * NSPLIT * G];
__device__ float  g_ps  [B * HKV * NSPLIT * G];
__device__ float  g_tl  [B * HKV * 3 * G];           // tail logits
__device__ float4 g_tv  [B * HKV * 3 * (D / 4)];     // tail V rows
__device__ int    g_cnt [B * HKV];                   // arrival counters (zero-init)

__device__ __forceinline__ void cp_async16(void* smem_dst, const void* gsrc) {
    uint32_t s = (uint32_t)__cvta_generic_to_shared(smem_dst);
    asm volatile("cp.async.cg.shared.global [%0], [%1], 16;\n" :: "r"(s), "l"(gsrc));
}
__device__ __forceinline__ void cp_async_commit() {
    asm volatile("cp.async.commit_group;\n" ::: "memory");
}
__device__ __forceinline__ void cp_async_wait_all() {
    asm volatile("cp.async.wait_group 0;\n" ::: "memory");
}

__device__ __forceinline__ float warp_sum(float v) {
    v += __shfl_xor_sync(0xffffffffu, v, 16);
    v += __shfl_xor_sync(0xffffffffu, v, 8);
    v += __shfl_xor_sync(0xffffffffu, v, 4);
    v += __shfl_xor_sync(0xffffffffu, v, 2);
    v += __shfl_xor_sync(0xffffffffu, v, 1);
    return v;
}
__device__ __forceinline__ float warp_max(float v) {
    v = fmaxf(v, __shfl_xor_sync(0xffffffffu, v, 16));
    v = fmaxf(v, __shfl_xor_sync(0xffffffffu, v, 8));
    v = fmaxf(v, __shfl_xor_sync(0xffffffffu, v, 4));
    v = fmaxf(v, __shfl_xor_sync(0xffffffffu, v, 2));
    v = fmaxf(v, __shfl_xor_sync(0xffffffffu, v, 1));
    return v;
}

// 4-head warp reduction in 11 shuffles. After xor16+xor8 each lane holds the
// sum over lanes congruent mod 8; lane-octet g finishes head g's sum.
__device__ __forceinline__ void reduce4(float x0, float x1, float x2, float x3,
                                        int l, float* dst /* &sm_p[t][0] */)
{
    x0 += __shfl_xor_sync(0xffffffffu, x0, 16);
    x1 += __shfl_xor_sync(0xffffffffu, x1, 16);
    x2 += __shfl_xor_sync(0xffffffffu, x2, 16);
    x3 += __shfl_xor_sync(0xffffffffu, x3, 16);
    x0 += __shfl_xor_sync(0xffffffffu, x0, 8);
    x1 += __shfl_xor_sync(0xffffffffu, x1, 8);
    x2 += __shfl_xor_sync(0xffffffffu, x2, 8);
    x3 += __shfl_xor_sync(0xffffffffu, x3, 8);
    const int g = l >> 3;
    float v = (g == 0) ? x0 : (g == 1) ? x1 : (g == 2) ? x2 : x3;
    v += __shfl_xor_sync(0xffffffffu, v, 4);
    v += __shfl_xor_sync(0xffffffffu, v, 2);
    v += __shfl_xor_sync(0xffffffffu, v, 1);
    if ((l & 7) == 0) dst[g] = v * SCALE;
}

// Merge: run by the last-arriving split CTA of (b, hkv). All inputs L2-hot.
__device__ __forceinline__ void merge_bh(int bh, int hkv,
    const float* __restrict__ sinks, float* __restrict__ out)
{
    const int tid  = threadIdx.x;
    const int base = bh * NSPLIT * G;
    const int b    = bh / HKV;

#pragma unroll
    for (int rep = 0; rep < 2; ++rep) {
        const int idx = rep * 256 + tid;          // 0..511
        const int g = idx >> 7, d = idx & 127;

        float pm[NSPLIT];
#pragma unroll
        for (int sp = 0; sp < NSPLIT; ++sp)
            pm[sp] = __ldcg(&g_pm[base + sp * G + g]);

        float tl[3];
#pragma unroll
        for (int t = 0; t < 3; ++t)
            tl[t] = __ldcg(&g_tl[(bh * 3 + t) * G + g]);

        const float sink = sinks[hkv * G + g];
        float M = sink;
#pragma unroll
        for (int sp = 0; sp < NSPLIT; ++sp) M = fmaxf(M, pm[sp]);
#pragma unroll
        for (int t = 0; t < 3; ++t) M = fmaxf(M, tl[t]);

        float S = __expf(sink - M);
        float num = 0.f;
#pragma unroll
        for (int sp = 0; sp < NSPLIT; ++sp) {
            const float w = __expf(pm[sp] - M);
            S += w * __ldcg(&g_ps[base + sp * G + g]);
            if (w > 0.f)
                num += w * __ldcg(&g_pacc[(size_t)(base + sp * G + g) * D + d]);
        }
        const float* tvf = (const float*)&g_tv[bh * 3 * (D / 4)];
#pragma unroll
        for (int t = 0; t < 3; ++t) {
            const float p = __expf(tl[t] - M);   // exactly 0 for invalid tail
            S   += p;
            num += p * tvf[t * D + d];
        }
        out[((size_t)b * HQ + hkv * G + g) * D + d] = num / S;
    }
}

struct __align__(16) SmemT {
    float4 v[64 * 32];        // 32 KB: V rows for tokens [0,64)
    float  acc[4][G][D];      // 8 KB combine buffers
    float  p[BS][G];          // 2 KB [token][head]
};

// ---------------------------------------------------------------------------
// One CTA per (b, hkv, page). Pass 1 streams K (+ cp.async first-half V into
// SMEM), block softmax, pass 2 streams second-half V via LDG + first half
// from SMEM. Fused last-CTA merge.
// ---------------------------------------------------------------------------
__global__ __launch_bounds__(256) void attn_kernel(
    const float* __restrict__ q,
    const float* __restrict__ cmp_kv,
    const int*   __restrict__ cmp_bt,
    const int*   __restrict__ seqused,
    const float* __restrict__ ori_kv,
    const int*   __restrict__ ori_bt,
    const float* __restrict__ sinks,
    float*       __restrict__ out)
{
    const int split = blockIdx.x % NSPLIT;
    const int bh    = blockIdx.x / NSPLIT;
    const int hkv   = bh % HKV;
    const int b     = bh / HKV;
    const int tid   = threadIdx.x;
    const int w     = tid >> 5;
    const int l     = tid & 31;

    const int seq     = seqused[b];
    const int cmp_len = seq >> 2;
    int cnt = cmp_len - split * BS;
    if (cnt > BS) cnt = BS;

    const int pmbase = (bh * NSPLIT + split) * G;

    __shared__ SmemT sm;

    if (cnt <= 0) {
        if (tid < G) { g_pm[pmbase + tid] = NEGINF; g_ps[pmbase + tid] = 0.f; }
    } else {
        const int page = cmp_bt[b * NCMPB + split];
        const float4* kbase = (const float4*)(cmp_kv + (size_t)page * PAGE_ELEMS + hkv * D);
        const float4* vbase = kbase + (BS * HKV * D) / 4;
        constexpr int TOKSTRIDE = HKV * D / 4;

        float4 qv[G];
        const float* qb = q + ((size_t)b * HQ + hkv * G) * D;
#pragma unroll
        for (int g = 0; g < G; ++g)
            qv[g] = ((const float4*)(qb + g * D))[l];

        // ---- pass 1: K dots + cp.async prefetch of V tokens [0,64) ----
        if (cnt == BS) {
#pragma unroll
            for (int i = 0; i < BS / 8; ++i) {
                const int t = w + i * 8;
                if (i < 8)
                    cp_async16(&sm.v[t * 32 + l], &vbase[(size_t)t * TOKSTRIDE + l]);
                const float4 k4 = kbase[(size_t)t * TOKSTRIDE + l];
                reduce4(qv[0].x*k4.x + qv[0].y*k4.y + qv[0].z*k4.z + qv[0].w*k4.w,
                        qv[1].x*k4.x + qv[1].y*k4.y + qv[1].z*k4.z + qv[1].w*k4.w,
                        qv[2].x*k4.x + qv[2].y*k4.y + qv[2].z*k4.z + qv[2].w*k4.w,
                        qv[3].x*k4.x + qv[3].y*k4.y + qv[3].z*k4.z + qv[3].w*k4.w,
                        l, &sm.p[t][0]);
            }
        } else {
            for (int t = w; t < cnt; t += 8) {
                if (t < 64)
                    cp_async16(&sm.v[t * 32 + l], &vbase[(size_t)t * TOKSTRIDE + l]);
                const float4 k4 = kbase[(size_t)t * TOKSTRIDE + l];
                reduce4(qv[0].x*k4.x + qv[0].y*k4.y + qv[0].z*k4.z + qv[0].w*k4.w,
                        qv[1].x*k4.x + qv[1].y*k4.y + qv[1].z*k4.z + qv[1].w*k4.w,
                        qv[2].x*k4.x + qv[2].y*k4.y + qv[2].z*k4.z + qv[2].w*k4.w,
                        qv[3].x*k4.x + qv[3].y*k4.y + qv[3].z*k4.z + qv[3].w*k4.w,
                        l, &sm.p[t][0]);
            }
        }
        cp_async_commit();
        __syncthreads();

        // ---- block softmax numerators (warp g owns head g) ----
        if (w < G) {
            float vals[4];
            float mx = NEGINF;
#pragma unroll
            for (int i = 0; i < 4; ++i) {
                const int t = l + i * 32;
                vals[i] = (t < cnt) ? sm.p[t][w] : NEGINF;
                mx = fmaxf(mx, vals[i]);
            }
            mx = warp_max(mx);
            float s = 0.f;
#pragma unroll
            for (int i = 0; i < 4; ++i) {
                const int t = l + i * 32;
                if (t < cnt) {
                    const float p = __expf(vals[i] - mx);
                    s += p;
                    sm.p[t][w] = p;
                }
            }
            s = warp_sum(s);
            if (l == 0) { g_pm[pmbase + w] = mx; g_ps[pmbase + w] = s; }
        }
        cp_async_wait_all();
        __syncthreads();

        // ---- pass 2: V accumulate; tokens [64,cnt) via LDG, [0,64) from SMEM ----
        float4 acc[G];
#pragma unroll
        for (int g = 0; g < G; ++g) acc[g] = make_float4(0.f, 0.f, 0.f, 0.f);

        if (cnt == BS) {
#pragma unroll
            for (int i = 0; i < 8; ++i) {
                const int t = 64 + w + i * 8;
                const float4 v4 = vbase[(size_t)t * TOKSTRIDE + l];
                const float4 p4 = *(const float4*)&sm.p[t][0];
                acc[0].x += p4.x * v4.x; acc[0].y += p4.x * v4.y;
                acc[0].z += p4.x * v4.z; acc[0].w += p4.x * v4.w;
                acc[1].x += p4.y * v4.x; acc[1].y += p4.y * v4.y;
                acc[1].z += p4.y * v4.z; acc[1].w += p4.y * v4.w;
                acc[2].x += p4.z * v4.x; acc[2].y += p4.z * v4.y;
                acc[2].z += p4.z * v4.z; acc[2].w += p4.z * v4.w;
                acc[3].x += p4.w * v4.x; acc[3].y += p4.w * v4.y;
                acc[3].z += p4.w * v4.z; acc[3].w += p4.w * v4.w;
            }
#pragma unroll
            for (int i = 0; i < 8; ++i) {
                const int t = w + i * 8;
                const float4 v4 = sm.v[t * 32 + l];
                const float4 p4 = *(const float4*)&sm.p[t][0];
                acc[0].x += p4.x * v4.x; acc[0].y += p4.x * v4.y;
                acc[0].z += p4.x * v4.z; acc[0].w += p4.x * v4.w;
                acc[1].x += p4.y * v4.x; acc[1].y += p4.y * v4.y;
                acc[1].z += p4.y * v4.z; acc[1].w += p4.y * v4.w;
                acc[2].x += p4.z * v4.x; acc[2].y += p4.z * v4.y;
                acc[2].z += p4.z * v4.z; acc[2].w += p4.z * v4.w;
                acc[3].x += p4.w * v4.x; acc[3].y += p4.w * v4.y;
                acc[3].z += p4.w * v4.z; acc[3].w += p4.w * v4.w;
            }
        } else {
            for (int t = 64 + w; t < cnt; t += 8) {
                const float4 v4 = vbase[(size_t)t * TOKSTRIDE + l];
                const float4 p4 = *(const float4*)&sm.p[t][0];
                acc[0].x += p4.x * v4.x; acc[0].y += p4.x * v4.y;
                acc[0].z += p4.x * v4.z; acc[0].w += p4.x * v4.w;
                acc[1].x += p4.y * v4.x; acc[1].y += p4.y * v4.y;
                acc[1].z += p4.y * v4.z; acc[1].w += p4.y * v4.w;
                acc[2].x += p4.z * v4.x; acc[2].y += p4.z * v4.y;
                acc[2].z += p4.z * v4.z; acc[2].w += p4.z * v4.w;
                acc[3].x += p4.w * v4.x; acc[3].y += p4.w * v4.y;
                acc[3].z += p4.w * v4.z; acc[3].w += p4.w * v4.w;
            }
            for (int t = w; t < cnt && t < 64; t += 8) {
                const float4 v4 = sm.v[t * 32 + l];
                const float4 p4 = *(const float4*)&sm.p[t][0];
                acc[0].x += p4.x * v4.x; acc[0].y += p4.x * v4.y;
                acc[0].z += p4.x * v4.z; acc[0].w += p4.x * v4.w;
                acc[1].x += p4.y * v4.x; acc[1].y += p4.y * v4.y;
                acc[1].z += p4.y * v4.z; acc[1].w += p4.y * v4.w;
                acc[2].x += p4.z * v4.x; acc[2].y += p4.z * v4.y;
                acc[2].z += p4.z * v4.z; acc[2].w += p4.z * v4.w;
                acc[3].x += p4.w * v4.x; acc[3].y += p4.w * v4.y;
                acc[3].z += p4.w * v4.z; acc[3].w += p4.w * v4.w;
            }
        }

        // ---- combine 8 warps via 4 buffers (warps 4-7 add into 0-3) ----
        if (w < 4) {
#pragma unroll
            for (int g = 0; g < G; ++g)
                ((float4*)sm.acc[w][g])[l] = acc[g];
        }
        __syncthreads();
        if (w >= 4) {
#pragma unroll
            for (int g = 0; g < G; ++g) {
                float4* dp = &((float4*)sm.acc[w - 4][g])[l];
                float4 x = *dp;
                x.x += acc[g].x; x.y += acc[g].y; x.z += acc[g].z; x.w += acc[g].w;
                *dp = x;
            }
        }
        __syncthreads();

        float* outp = g_pacc + (size_t)pmbase * D;
#pragma unroll
        for (int rep = 0; rep < 2; ++rep) {
            const int idx = rep * 256 + tid;
            const int g = idx >> 7, d = idx & 127;
            float v = sm.acc[0][g][d] + sm.acc[1][g][d]
                    + sm.acc[2][g][d] + sm.acc[3][g][d];
            outp[idx] = v;
        }

        // ---- split 0 also computes the <=3-token original-cache tail ----
        if (split == 0 && w < 3) {
            const int cmp_base = cmp_len << 2;
            const int ntail    = seq - cmp_base;     // 0..3
            float4* tvrow = &g_tv[(bh * 3 + w) * (D / 4)];
            if (w < ntail) {
                const int pos   = cmp_base + w;
                const int opage = ori_bt[b * NORIB + (pos >> 7)];
                const float* kp = ori_kv + (size_t)opage * PAGE_ELEMS
                                  + (size_t)(pos & 127) * HKV * D + hkv * D;
                const float4 k4 = ((const float4*)kp)[l];
                const float4 v4 = ((const float4*)(kp + BS * HKV * D))[l];
                tvrow[l] = v4;
#pragma unroll
                for (int g = 0; g < G; ++g) {
                    float x = qv[g].x * k4.x + qv[g].y * k4.y + qv[g].z * k4.z + qv[g].w * k4.w;
                    x = warp_sum(x);
                    if (l == g) g_tl[(bh * 3 + w) * G + g] = x * SCALE;
                }
            } else {
                if (l < G) g_tl[(bh * 3 + w) * G + l] = NEGINF;
                tvrow[l] = make_float4(0.f, 0.f, 0.f, 0.f);
            }
        }
    }

    // ---- last-CTA merge (threadFenceReduction pattern) ----
    __shared__ int s_last;
    __threadfence();
    if (tid == 0) {
        const int v = atomicAdd(&g_cnt[bh], 1);
        const int last = (v == NSPLIT - 1);
        if (last) g_cnt[bh] = 0;     // reset for next graph replay
        s_last = last;
    }
    __syncthreads();
    if (s_last) {
        __threadfence();
        merge_bh(bh, hkv, sinks, out);
    }
}

extern "C" void kernel_launch(void* const* d_in, const int* in_sizes, int n_in,
                              void* d_out, int out_size) {
    const float* q       = (const float*)d_in[0];
    const float* cmp_kv  = (const float*)d_in[1];
    const float* sinks   = (const float*)d_in[2];
    const int*   cmp_bt  = (const int*)d_in[3];
    const int*   seqused = (const int*)d_in[4];
    const float* ori_kv  = (const float*)d_in[5];
    const int*   ori_bt  = (const int*)d_in[6];
    float* out = (float*)d_out;

    attn_kernel<<<B * HKV * NSPLIT, 256>>>(q, cmp_kv, cmp_bt, seqused,
                                           ori_kv, ori_bt, sinks, out);
}